// round 2
// baseline (speedup 1.0000x reference)
#include <cuda_runtime.h>
#include <cstdint>
#include <math.h>

#define B_  64
#define T_  1024
#define E_  512
#define A_  128
#define NF_ 32
#define K_  31
#define J_  (2*K_)   // 62 combined conv taps

// ---------------- scratch (no allocations allowed) ----------------
__device__ float g_pq[B_*A_];          // processed_query [B, A]
__device__ float g_wcomb[J_*A_];       // folded Wl @ conv_w, layout [j][a]
__device__ float g_energies[B_*T_];    // pre-softmax energies

// ---------------- tiny prep kernels ----------------
__global__ void pq_kernel(const float* __restrict__ ahs, const float* __restrict__ Wq) {
    __shared__ float sh[A_];
    const int b = blockIdx.x, a = threadIdx.x;
    sh[a] = ahs[b*A_ + a];
    __syncthreads();
    const float* wr = Wq + a*A_;
    float s = 0.f;
    #pragma unroll 8
    for (int i = 0; i < A_; i++) s += sh[i]*wr[i];
    g_pq[b*A_ + a] = s;
}

// Wcomb[j=c*31+k][a] = sum_f Wl[a,f] * conv_w[f,c,k]
__global__ void wcomb_kernel(const float* __restrict__ Wl, const float* __restrict__ convw) {
    const int j = blockIdx.x;        // 0..61
    const int a = threadIdx.x;       // 0..127
    const int c = j / K_, k = j % K_;
    float s = 0.f;
    #pragma unroll
    for (int f = 0; f < NF_; f++) s += Wl[a*NF_ + f]*convw[f*(2*K_) + c*K_ + k];
    g_wcomb[j*A_ + a] = s;
}

// ---------------- fused energies kernel ----------------
// One CTA = (b, 128-wide t tile). 256 threads, 8x8 register microtiles.
// acc[t][a] = sum_e PM[b,t,e]*Wm[a,e]  (stage 1, E=512)
//           + sum_j awc_window[t,j]*Wcomb[j,a]  (stage 2, J=62)
// energy[t] = sum_a v[a]*tanh(acc + pq[b,a])
__global__ __launch_bounds__(256, 2)
void energies_kernel(const float* __restrict__ pmem,
                     const float* __restrict__ Wm,
                     const float* __restrict__ awc,
                     const float* __restrict__ v)
{
    __shared__ float buf[2*32*129];      // 8256 floats = 33KB, reused across stages
    __shared__ float s_pq[A_], s_v[A_];
    float (*sA)[129] = (float(*)[129])buf;            // [e][t]
    float (*sB)[129] = (float(*)[129])(buf + 32*129); // [e][a]

    const int tid = threadIdx.x;
    const int tx = tid & 15, ty = tid >> 4;
    const int b = blockIdx.y;
    const int t0 = blockIdx.x * 128;

    if (tid < A_) { s_pq[tid] = g_pq[b*A_ + tid]; s_v[tid] = v[tid]; }

    float acc[8][8];
    #pragma unroll
    for (int i = 0; i < 8; i++)
        #pragma unroll
        for (int j = 0; j < 8; j++) acc[i][j] = 0.f;

    const float* PMb = pmem + ((size_t)b*T_ + t0)*E_;

    // ---- stage 1: pm GEMM, e-chunks of 32 ----
    for (int e0 = 0; e0 < E_; e0 += 32) {
        #pragma unroll
        for (int q = 0; q < 4; q++) {
            int idx = tid + 256*q;           // float4 index
            int r  = idx >> 3;               // row (t or a), 0..127
            int e4 = idx & 7;                // float4 within 32-e chunk
            float4 x = *(const float4*)(PMb + (size_t)r*E_ + e0 + e4*4);
            sA[e4*4+0][r] = x.x; sA[e4*4+1][r] = x.y;
            sA[e4*4+2][r] = x.z; sA[e4*4+3][r] = x.w;
            float4 y = *(const float4*)(Wm + (size_t)r*E_ + e0 + e4*4);
            sB[e4*4+0][r] = y.x; sB[e4*4+1][r] = y.y;
            sB[e4*4+2][r] = y.z; sB[e4*4+3][r] = y.w;
        }
        __syncthreads();
        #pragma unroll
        for (int e = 0; e < 32; e++) {
            float tF[8], aF[8];
            #pragma unroll
            for (int i = 0; i < 8; i++) { tF[i] = sA[e][ty + 16*i]; aF[i] = sB[e][tx + 16*i]; }
            #pragma unroll
            for (int i = 0; i < 8; i++)
                #pragma unroll
                for (int j = 0; j < 8; j++) acc[i][j] += tF[i]*aF[j];
        }
        __syncthreads();
    }

    // ---- stage 2: location term (62-deep sliding-window GEMM) ----
    float* sW   = buf;           // [62][128] = 7936 floats
    float* sAwc = buf + 7936;    // [2][160]  window, padded
    for (int i = tid; i < J_*A_; i += 256) sW[i] = g_wcomb[i];
    for (int i = tid; i < 320; i += 256) {
        int c = i / 160, x = i % 160;
        int t = t0 - 15 + x;
        float vv = 0.f;
        if (x < 158 && t >= 0 && t < T_) vv = awc[((size_t)b*2 + c)*T_ + t];
        sAwc[c*160 + x] = vv;
    }
    __syncthreads();
    for (int j = 0; j < J_; j++) {
        const int c = (j >= K_) ? 1 : 0;
        const int k = j - c*K_;
        float tF[8], aF[8];
        #pragma unroll
        for (int i = 0; i < 8; i++) {
            aF[i] = sW[j*A_ + tx + 16*i];
            tF[i] = sAwc[c*160 + ty + 16*i + k];
        }
        #pragma unroll
        for (int i = 0; i < 8; i++)
            #pragma unroll
            for (int jj = 0; jj < 8; jj++) acc[i][jj] += tF[i]*aF[jj];
    }

    // ---- epilogue: tanh, v-dot, cross-tx reduce ----
    #pragma unroll
    for (int i = 0; i < 8; i++) {
        float s = 0.f;
        #pragma unroll
        for (int jj = 0; jj < 8; jj++) {
            const int a = tx + 16*jj;
            s += s_v[a]*tanhf(acc[i][jj] + s_pq[a]);
        }
        s += __shfl_xor_sync(0xffffffffu, s, 1);
        s += __shfl_xor_sync(0xffffffffu, s, 2);
        s += __shfl_xor_sync(0xffffffffu, s, 4);
        s += __shfl_xor_sync(0xffffffffu, s, 8);
        if (tx == 0) g_energies[b*T_ + t0 + ty + 16*i] = s;
    }
}

// ---------------- masked softmax over T ----------------
// mask is jax bool -> transferred as int32 (harness has no bool dtype)
__global__ void softmax_kernel(const int* __restrict__ mask, float* __restrict__ wout) {
    const int b = blockIdx.x, tid = threadIdx.x;
    __shared__ float red[256];
    float e[4];
    float mx = -INFINITY;
    #pragma unroll
    for (int q = 0; q < 4; q++) {
        int t = tid + 256*q;
        float ev = g_energies[b*T_ + t];
        if (mask[b*T_ + t] != 0) ev = -INFINITY;
        e[q] = ev;
        mx = fmaxf(mx, ev);
    }
    red[tid] = mx; __syncthreads();
    for (int s = 128; s > 0; s >>= 1) {
        if (tid < s) red[tid] = fmaxf(red[tid], red[tid + s]);
        __syncthreads();
    }
    const float m = red[0];
    __syncthreads();
    float ex[4], sum = 0.f;
    #pragma unroll
    for (int q = 0; q < 4; q++) {
        ex[q] = (e[q] == -INFINITY) ? 0.f : expf(e[q] - m);
        sum += ex[q];
    }
    red[tid] = sum; __syncthreads();
    for (int s = 128; s > 0; s >>= 1) {
        if (tid < s) red[tid] += red[tid + s];
        __syncthreads();
    }
    const float inv = 1.f / red[0];
    #pragma unroll
    for (int q = 0; q < 4; q++) wout[b*T_ + tid + 256*q] = ex[q]*inv;
}

// ---------------- context = weights @ memory ----------------
// Exploits w[t]==0 at masked positions (uniform branch) to halve HBM traffic.
__global__ void context_kernel(const float* __restrict__ mem,
                               const float* __restrict__ w,
                               float* __restrict__ ctx)
{
    __shared__ float sw[T_];
    const int b = blockIdx.y;
    const int e = blockIdx.x*256 + threadIdx.x;
    for (int i = threadIdx.x; i < T_; i += 256) sw[i] = w[b*T_ + i];
    __syncthreads();
    const float* mb = mem + (size_t)b*T_*E_ + e;
    float a0 = 0.f, a1 = 0.f, a2 = 0.f, a3 = 0.f;
    for (int t = 0; t < T_; t += 4) {
        float w0 = sw[t], w1 = sw[t+1], w2 = sw[t+2], w3 = sw[t+3];
        if (w0 != 0.f) a0 += w0*mb[(size_t)(t  )*E_];
        if (w1 != 0.f) a1 += w1*mb[(size_t)(t+1)*E_];
        if (w2 != 0.f) a2 += w2*mb[(size_t)(t+2)*E_];
        if (w3 != 0.f) a3 += w3*mb[(size_t)(t+3)*E_];
    }
    ctx[b*E_ + e] = (a0 + a1) + (a2 + a3);
}

// ---------------- launch ----------------
extern "C" void kernel_launch(void* const* d_in, const int* in_sizes, int n_in,
                              void* d_out, int out_size)
{
    const float* ahs   = (const float*)d_in[0];   // [B, A]
    const float* mem   = (const float*)d_in[1];   // [B, T, E]
    const float* pmem  = (const float*)d_in[2];   // [B, T, E]
    const float* awc   = (const float*)d_in[3];   // [B, 2, T]
    const int*   mask  = (const int*)d_in[4];     // [B, T] bool -> int32
    const float* Wq    = (const float*)d_in[5];   // [A, A]
    const float* Wm    = (const float*)d_in[6];   // [A, E]
    const float* v     = (const float*)d_in[7];   // [1, A]
    const float* convw = (const float*)d_in[8];   // [NF, 2, K]
    const float* Wl    = (const float*)d_in[9];   // [A, NF]

    float* out_ctx = (float*)d_out;            // [B, E]
    float* out_w   = (float*)d_out + B_*E_;    // [B, T]

    pq_kernel<<<B_, A_>>>(ahs, Wq);
    wcomb_kernel<<<J_, A_>>>(Wl, convw);
    energies_kernel<<<dim3(T_/128, B_), 256>>>(pmem, Wm, awc, v);
    softmax_kernel<<<B_, 256>>>(mask, out_w);
    context_kernel<<<dim3(E_/256, B_), 256>>>(mem, out_w, out_ctx);
}

// round 4
// speedup vs baseline: 1.5127x; 1.5127x over previous
#include <cuda_runtime.h>
#include <cuda_bf16.h>
#include <cstdint>
#include <math.h>

#define B_  64
#define T_  1024
#define E_  512
#define A_  128
#define NF_ 32
#define K_  31

// ---------------- smem layout for the MMA kernel (dynamic) ----------------
#define OFF_AHI 0
#define OFF_ALO 16384
#define OFF_BHI 32768
#define OFF_BLO 49152
#define OFF_AWC  65536           // 320 floats
#define OFF_PQ   66816           // 128 floats
#define OFF_V    67328           // 128 floats
#define OFF_PART 67840           // 512 floats
#define SMEM_TOTAL 69888

// ---------------- scratch ----------------
__device__ float g_pq[B_*A_];
__device__ float g_energies[B_*T_];
__device__ __align__(16) __nv_bfloat16 g_wmhi[A_*E_];
__device__ __align__(16) __nv_bfloat16 g_wmlo[A_*E_];
__device__ __align__(16) __nv_bfloat16 g_wclhi[A_*64];
__device__ __align__(16) __nv_bfloat16 g_wcllo[A_*64];

// ---------------- helpers ----------------
__device__ __forceinline__ uint32_t smem_u32(const void* p) {
    uint32_t a;
    asm("{ .reg .u64 t; cvta.to.shared.u64 t, %1; cvt.u32.u64 %0, t; }" : "=r"(a) : "l"(p));
    return a;
}
#define STS128(addr, a, b, c, d) \
    asm volatile("st.shared.v4.b32 [%0], {%1,%2,%3,%4};" :: "r"(addr), "r"(a), "r"(b), "r"(c), "r"(d) : "memory")

__device__ __forceinline__ void ldsm_x4(uint32_t (&r)[4], uint32_t addr) {
    asm volatile("ldmatrix.sync.aligned.m8n8.x4.shared.b16 {%0,%1,%2,%3}, [%4];"
        : "=r"(r[0]), "=r"(r[1]), "=r"(r[2]), "=r"(r[3]) : "r"(addr));
}
__device__ __forceinline__ void mma_bf16(float (&c)[4], const uint32_t (&a)[4],
                                         uint32_t b0, uint32_t b1) {
    asm volatile("mma.sync.aligned.m16n8k16.row.col.f32.bf16.bf16.f32 "
        "{%0,%1,%2,%3}, {%4,%5,%6,%7}, {%8,%9}, {%0,%1,%2,%3};"
        : "+f"(c[0]), "+f"(c[1]), "+f"(c[2]), "+f"(c[3])
        : "r"(a[0]), "r"(a[1]), "r"(a[2]), "r"(a[3]), "r"(b0), "r"(b1));
}
// byte address inside a 128-row x 128-byte smem tile, SW128 swizzle
__device__ __forceinline__ uint32_t tile_addr(uint32_t base, int row, int kbyte) {
    uint32_t off = (uint32_t)(row*128 + kbyte);
    return base + (off ^ ((off >> 3) & 0x70));
}
// ldmatrix.x4 lane address for 16x16 bf16 block at (rb, kb elements)
__device__ __forceinline__ uint32_t ldsm_addr(uint32_t base, int rb, int kb, int lane) {
    int row = rb + (lane & 15);
    int kbyte = (kb + (lane >> 4)*8)*2;
    return tile_addr(base, row, kbyte);
}

__device__ __forceinline__ void split2(float a, float b, uint32_t& h, uint32_t& l) {
    __nv_bfloat16 ha = __float2bfloat16_rn(a), hb = __float2bfloat16_rn(b);
    __nv_bfloat16 la = __float2bfloat16_rn(a - __bfloat162float(ha));
    __nv_bfloat16 lb = __float2bfloat16_rn(b - __bfloat162float(hb));
    __nv_bfloat162 hp; hp.x = ha; hp.y = hb;
    __nv_bfloat162 lp; lp.x = la; lp.y = lb;
    h = *reinterpret_cast<uint32_t*>(&hp);
    l = *reinterpret_cast<uint32_t*>(&lp);
}
__device__ __forceinline__ float tanh_fast(float x) {
    float e = __expf(fminf(fmaxf(2.f*x, -30.f), 30.f));
    return 1.f - __fdividef(2.f, e + 1.f);
}
__device__ __forceinline__ float locval(const float* s_awc, int r, int j) {
    if (j >= 62) return 0.f;
    int c = (j >= 31) ? 1 : 0;
    int k = j - c*31;
    return s_awc[c*160 + r + k];
}

// ---------------- prep kernels ----------------
__global__ void pq_kernel(const float* __restrict__ ahs, const float* __restrict__ Wq) {
    __shared__ float sh[A_];
    const int b = blockIdx.x, a = threadIdx.x;
    sh[a] = ahs[b*A_ + a];
    __syncthreads();
    const float* wr = Wq + a*A_;
    float s = 0.f;
    #pragma unroll 8
    for (int i = 0; i < A_; i++) s += sh[i]*wr[i];
    g_pq[b*A_ + a] = s;
}

__global__ void wm_split_kernel(const float* __restrict__ Wm) {
    int i = blockIdx.x*256 + threadIdx.x;
    float x = Wm[i];
    __nv_bfloat16 h = __float2bfloat16_rn(x);
    g_wmhi[i] = h;
    g_wmlo[i] = __float2bfloat16_rn(x - __bfloat162float(h));
}

// g_wcl[a][j] = sum_f Wl[a,f]*conv_w[f,c,k], j=c*31+k, padded to 64
__global__ void wcl_kernel(const float* __restrict__ Wl, const float* __restrict__ convw) {
    const int j = blockIdx.x;   // 0..63
    const int a = threadIdx.x;  // 0..127
    float s = 0.f;
    if (j < 62) {
        int c = j / K_, k = j % K_;
        #pragma unroll
        for (int f = 0; f < NF_; f++) s += Wl[a*NF_ + f]*convw[f*(2*K_) + c*K_ + k];
    }
    __nv_bfloat16 h = __float2bfloat16_rn(s);
    g_wclhi[a*64 + j] = h;
    g_wcllo[a*64 + j] = __float2bfloat16_rn(s - __bfloat162float(h));
}

// ---------------- HMMA energies kernel ----------------
// CTA = (b, 128-t tile). D[t][a] = sum_{k<576} A[t,k]*B[a,k], bf16 hi/lo 3-term.
// Chunks 0..7: pm (PM vs Wm). Chunk 8: folded location term.
// 8 warps: warp_m = wid&1 (64 t rows), warp_n = wid>>1 (32 a cols).
__global__ __launch_bounds__(256, 1)
void energies_mma_kernel(const float* __restrict__ pmem,
                         const float* __restrict__ awc,
                         const float* __restrict__ v)
{
    extern __shared__ char smem[];
    const uint32_t sb = smem_u32(smem);
    const int tid = threadIdx.x;
    const int wid = tid >> 5, lane = tid & 31;
    const int b = blockIdx.y, t0 = blockIdx.x*128;
    const int warp_m = wid & 1, warp_n = wid >> 1;
    const int mb = warp_m*64, nb = warp_n*32;

    float* s_awc  = (float*)(smem + OFF_AWC);
    float* s_pq   = (float*)(smem + OFF_PQ);
    float* s_v    = (float*)(smem + OFF_V);
    float* s_part = (float*)(smem + OFF_PART);

    for (int i = tid; i < 320; i += 256) {
        int c = i / 160, x = i % 160, t = t0 - 15 + x;
        s_awc[i] = (x < 158 && t >= 0 && t < T_) ? awc[((size_t)b*2 + c)*T_ + t] : 0.f;
    }
    if (tid < A_) { s_pq[tid] = g_pq[b*A_ + tid]; s_v[tid] = v[tid]; }

    float acc[4][4][4];
    #pragma unroll
    for (int i = 0; i < 4; i++)
        #pragma unroll
        for (int j = 0; j < 4; j++)
            #pragma unroll
            for (int q = 0; q < 4; q++) acc[i][j][q] = 0.f;

    const float* PMb = pmem + ((size_t)b*T_ + t0)*E_;

    for (int ch = 0; ch < 9; ch++) {
        // ---- stage A tile: 128 rows x 64 bf16 (hi & lo), SW128 swizzled ----
        if (ch < 8) {
            const int e0 = ch*64;
            #pragma unroll
            for (int it = 0; it < 4; it++) {
                int idx = tid + 256*it;
                int r = idx >> 3, g = idx & 7;
                const float4* p = (const float4*)(PMb + (size_t)r*E_ + e0 + g*8);
                float4 x0 = p[0], x1 = p[1];
                uint32_t h0,h1,h2,h3,l0,l1,l2,l3;
                split2(x0.x, x0.y, h0, l0); split2(x0.z, x0.w, h1, l1);
                split2(x1.x, x1.y, h2, l2); split2(x1.z, x1.w, h3, l3);
                uint32_t a_hi = tile_addr(sb + OFF_AHI, r, g*16);
                uint32_t a_lo = tile_addr(sb + OFF_ALO, r, g*16);
                STS128(a_hi, h0, h1, h2, h3);
                STS128(a_lo, l0, l1, l2, l3);
            }
        } else {
            const int r = tid >> 1, jb = (tid & 1)*32;
            #pragma unroll
            for (int jj = 0; jj < 32; jj += 8) {
                uint32_t hw[4], lw[4];
                #pragma unroll
                for (int q = 0; q < 4; q++) {
                    int j0 = jb + jj + 2*q;
                    split2(locval(s_awc, r, j0), locval(s_awc, r, j0 + 1), hw[q], lw[q]);
                }
                uint32_t a_hi = tile_addr(sb + OFF_AHI, r, (jb + jj)*2);
                uint32_t a_lo = tile_addr(sb + OFF_ALO, r, (jb + jj)*2);
                STS128(a_hi, hw[0], hw[1], hw[2], hw[3]);
                STS128(a_lo, lw[0], lw[1], lw[2], lw[3]);
            }
        }
        // ---- stage B tile: 128 rows x 64 bf16 (hi & lo), precomputed bf16 ----
        {
            const __nv_bfloat16* bh; const __nv_bfloat16* bl; int stride, be0;
            if (ch < 8) { bh = g_wmhi;  bl = g_wmlo;  stride = E_; be0 = ch*64; }
            else        { bh = g_wclhi; bl = g_wcllo; stride = 64; be0 = 0; }
            #pragma unroll
            for (int it = 0; it < 4; it++) {
                int idx = tid + 256*it;
                int r = idx >> 3, g = idx & 7;
                uint4 hw = ((const uint4*)(bh + (size_t)r*stride + be0))[g];
                uint4 lw = ((const uint4*)(bl + (size_t)r*stride + be0))[g];
                uint32_t b_hi = tile_addr(sb + OFF_BHI, r, g*16);
                uint32_t b_lo = tile_addr(sb + OFF_BLO, r, g*16);
                STS128(b_hi, hw.x, hw.y, hw.z, hw.w);
                STS128(b_lo, lw.x, lw.y, lw.z, lw.w);
            }
        }
        __syncthreads();

        // ---- compute: 4 k16 steps x (hh + hl + lh) ----
        #pragma unroll
        for (int ks = 0; ks < 4; ks++) {
            const int kb = ks*16;
            uint32_t ah[4][4], al[4][4], bhf[2][4], blf[2][4];
            #pragma unroll
            for (int i = 0; i < 4; i++) {
                ldsm_x4(ah[i], ldsm_addr(sb + OFF_AHI, mb + 16*i, kb, lane));
                ldsm_x4(al[i], ldsm_addr(sb + OFF_ALO, mb + 16*i, kb, lane));
            }
            #pragma unroll
            for (int j2 = 0; j2 < 2; j2++) {
                ldsm_x4(bhf[j2], ldsm_addr(sb + OFF_BHI, nb + 16*j2, kb, lane));
                ldsm_x4(blf[j2], ldsm_addr(sb + OFF_BLO, nb + 16*j2, kb, lane));
            }
            #pragma unroll
            for (int i = 0; i < 4; i++) {
                #pragma unroll
                for (int j = 0; j < 4; j++) {
                    const int j2 = j >> 1, jo = j & 1;
                    mma_bf16(acc[i][j], ah[i], bhf[j2][jo], bhf[j2][jo+2]);
                    mma_bf16(acc[i][j], ah[i], blf[j2][jo], blf[j2][jo+2]);
                    mma_bf16(acc[i][j], al[i], bhf[j2][jo], bhf[j2][jo+2]);
                }
            }
        }
        __syncthreads();
    }

    // ---- epilogue: energy[t] = sum_a v[a]*tanh(D[t][a] + pq[a]) ----
    #pragma unroll
    for (int i = 0; i < 4; i++) {
        #pragma unroll
        for (int half = 0; half < 2; half++) {
            float s = 0.f;
            #pragma unroll
            for (int j = 0; j < 4; j++) {
                const int a0 = nb + j*8 + (lane & 3)*2;
                float x0 = acc[i][j][half*2+0] + s_pq[a0];
                float x1 = acc[i][j][half*2+1] + s_pq[a0+1];
                s += s_v[a0]*tanh_fast(x0) + s_v[a0+1]*tanh_fast(x1);
            }
            s += __shfl_xor_sync(0xffffffffu, s, 1);
            s += __shfl_xor_sync(0xffffffffu, s, 2);
            if ((lane & 3) == 0) {
                int row = mb + i*16 + (lane >> 2) + half*8;
                s_part[row*4 + warp_n] = s;
            }
        }
    }
    __syncthreads();
    if (tid < 128) {
        const float* p = s_part + tid*4;
        g_energies[(size_t)b*T_ + t0 + tid] = (p[0] + p[1]) + (p[2] + p[3]);
    }
}

// ---------------- masked softmax over T ----------------
__global__ void softmax_kernel(const int* __restrict__ mask, float* __restrict__ wout) {
    const int b = blockIdx.x, tid = threadIdx.x;
    __shared__ float red[256];
    float e[4];
    float mx = -INFINITY;
    #pragma unroll
    for (int q = 0; q < 4; q++) {
        int t = tid + 256*q;
        float ev = g_energies[b*T_ + t];
        if (mask[b*T_ + t] != 0) ev = -INFINITY;
        e[q] = ev;
        mx = fmaxf(mx, ev);
    }
    red[tid] = mx; __syncthreads();
    for (int s = 128; s > 0; s >>= 1) {
        if (tid < s) red[tid] = fmaxf(red[tid], red[tid + s]);
        __syncthreads();
    }
    const float m = red[0];
    __syncthreads();
    float ex[4], sum = 0.f;
    #pragma unroll
    for (int q = 0; q < 4; q++) {
        ex[q] = (e[q] == -INFINITY) ? 0.f : expf(e[q] - m);
        sum += ex[q];
    }
    red[tid] = sum; __syncthreads();
    for (int s = 128; s > 0; s >>= 1) {
        if (tid < s) red[tid] += red[tid + s];
        __syncthreads();
    }
    const float inv = 1.f / red[0];
    #pragma unroll
    for (int q = 0; q < 4; q++) wout[b*T_ + tid + 256*q] = ex[q]*inv;
}

// ---------------- context = weights @ memory ----------------
__global__ void context_kernel(const float* __restrict__ mem,
                               const float* __restrict__ w,
                               float* __restrict__ ctx)
{
    __shared__ float sw[T_];
    const int b = blockIdx.y;
    const int e = blockIdx.x*256 + threadIdx.x;
    for (int i = threadIdx.x; i < T_; i += 256) sw[i] = w[b*T_ + i];
    __syncthreads();
    const float* mb = mem + (size_t)b*T_*E_ + e;
    float a0 = 0.f, a1 = 0.f, a2 = 0.f, a3 = 0.f;
    for (int t = 0; t < T_; t += 4) {
        float w0 = sw[t], w1 = sw[t+1], w2 = sw[t+2], w3 = sw[t+3];
        if (w0 != 0.f) a0 += w0*mb[(size_t)(t  )*E_];
        if (w1 != 0.f) a1 += w1*mb[(size_t)(t+1)*E_];
        if (w2 != 0.f) a2 += w2*mb[(size_t)(t+2)*E_];
        if (w3 != 0.f) a3 += w3*mb[(size_t)(t+3)*E_];
    }
    ctx[b*E_ + e] = (a0 + a1) + (a2 + a3);
}

// ---------------- launch ----------------
extern "C" void kernel_launch(void* const* d_in, const int* in_sizes, int n_in,
                              void* d_out, int out_size)
{
    const float* ahs   = (const float*)d_in[0];   // [B, A]
    const float* mem   = (const float*)d_in[1];   // [B, T, E]
    const float* pmem  = (const float*)d_in[2];   // [B, T, E]
    const float* awc   = (const float*)d_in[3];   // [B, 2, T]
    const int*   mask  = (const int*)d_in[4];     // [B, T] bool -> int32
    const float* Wq    = (const float*)d_in[5];   // [A, A]
    const float* Wm    = (const float*)d_in[6];   // [A, E]
    const float* v     = (const float*)d_in[7];   // [1, A]
    const float* convw = (const float*)d_in[8];   // [NF, 2, K]
    const float* Wl    = (const float*)d_in[9];   // [A, NF]

    float* out_ctx = (float*)d_out;            // [B, E]
    float* out_w   = (float*)d_out + B_*E_;    // [B, T]

    cudaFuncSetAttribute(energies_mma_kernel,
                         cudaFuncAttributeMaxDynamicSharedMemorySize, SMEM_TOTAL);

    pq_kernel<<<B_, A_>>>(ahs, Wq);
    wm_split_kernel<<<(A_*E_)/256, 256>>>(Wm);
    wcl_kernel<<<64, A_>>>(Wl, convw);
    energies_mma_kernel<<<dim3(T_/128, B_), 256, SMEM_TOTAL>>>(pmem, awc, v);
    softmax_kernel<<<B_, 256>>>(mask, out_w);
    context_kernel<<<dim3(E_/256, B_), 256>>>(mem, out_w, out_ctx);
}

// round 5
// speedup vs baseline: 3.2830x; 2.1703x over previous
#include <cuda_runtime.h>
#include <cuda_fp16.h>
#include <cstdint>
#include <math.h>

#define B_  64
#define T_  1024
#define E_  512
#define A_  128
#define NF_ 32
#define K_  31
#define SEG_ 8

// ---------------- smem layout (dynamic) ----------------
#define OFF_AH0 0
#define OFF_AL0 16384
#define OFF_AH1 32768
#define OFF_AL1 49152
#define OFF_B0  65536
#define OFF_B1  81920
#define OFF_AWC 98304            // 320 floats
#define OFF_PQ  99584            // 128 floats
#define OFF_V   100096           // 128 floats
#define OFF_PART 100608          // 512 floats
#define SMEM_TOTAL 102656

// ---------------- scratch ----------------
__device__ float g_pq[B_*A_];
__device__ float g_energies[B_*T_];
__device__ __align__(16) __half g_wmh[A_*E_];     // fp16(Wm)
__device__ __align__(16) __half g_wclh[A_*64];    // fp16(folded Wl@conv_w), [a][j] padded 64
__device__ float g_cpart[SEG_*B_*E_];

// ---------------- helpers ----------------
__device__ __forceinline__ uint32_t smem_u32(const void* p) {
    uint32_t a;
    asm("{ .reg .u64 t; cvta.to.shared.u64 t, %1; cvt.u32.u64 %0, t; }" : "=r"(a) : "l"(p));
    return a;
}
#define STS128(addr, a, b, c, d) \
    asm volatile("st.shared.v4.b32 [%0], {%1,%2,%3,%4};" :: "r"(addr), "r"(a), "r"(b), "r"(c), "r"(d) : "memory")
#define CPASYNC16(dst, src) \
    asm volatile("cp.async.ca.shared.global [%0], [%1], 16;" :: "r"(dst), "l"(src) : "memory")
#define CPCOMMIT() asm volatile("cp.async.commit_group;" ::: "memory")

__device__ __forceinline__ void ldsm_x4(uint32_t (&r)[4], uint32_t addr) {
    asm volatile("ldmatrix.sync.aligned.m8n8.x4.shared.b16 {%0,%1,%2,%3}, [%4];"
        : "=r"(r[0]), "=r"(r[1]), "=r"(r[2]), "=r"(r[3]) : "r"(addr));
}
__device__ __forceinline__ void mma_f16(float (&c)[4], const uint32_t (&a)[4],
                                        uint32_t b0, uint32_t b1) {
    asm volatile("mma.sync.aligned.m16n8k16.row.col.f32.f16.f16.f32 "
        "{%0,%1,%2,%3}, {%4,%5,%6,%7}, {%8,%9}, {%0,%1,%2,%3};"
        : "+f"(c[0]), "+f"(c[1]), "+f"(c[2]), "+f"(c[3])
        : "r"(a[0]), "r"(a[1]), "r"(a[2]), "r"(a[3]), "r"(b0), "r"(b1));
}
// byte address inside a 128-row x 128-byte smem tile, SW128 swizzle
__device__ __forceinline__ uint32_t tile_addr(uint32_t base, int row, int kbyte) {
    uint32_t off = (uint32_t)(row*128 + kbyte);
    return base + (off ^ ((off >> 3) & 0x70));
}
__device__ __forceinline__ uint32_t ldsm_addr(uint32_t base, int rb, int kb, int lane) {
    int row = rb + (lane & 15);
    int kbyte = (kb + (lane >> 4)*8)*2;
    return tile_addr(base, row, kbyte);
}
__device__ __forceinline__ void split2h(float a, float b, uint32_t& h, uint32_t& l) {
    __half ha = __float2half_rn(a), hb = __float2half_rn(b);
    __half la = __float2half_rn(a - __half2float(ha));
    __half lb = __float2half_rn(b - __half2float(hb));
    __half2 hp = __halves2half2(ha, hb), lp = __halves2half2(la, lb);
    h = *reinterpret_cast<uint32_t*>(&hp);
    l = *reinterpret_cast<uint32_t*>(&lp);
}
__device__ __forceinline__ float tanh_fast(float x) {
    float e = __expf(fminf(fmaxf(2.f*x, -30.f), 30.f));
    return 1.f - __fdividef(2.f, e + 1.f);
}
__device__ __forceinline__ float locval(const float* s_awc, int r, int j) {
    if (j >= 62) return 0.f;
    int c = (j >= 31) ? 1 : 0;
    int k = j - c*31;
    return s_awc[c*160 + r + k];
}

// ---------------- prep kernels ----------------
__global__ void pq_kernel(const float* __restrict__ ahs, const float* __restrict__ Wq) {
    __shared__ float sh[A_];
    const int b = blockIdx.x, a = threadIdx.x;
    sh[a] = ahs[b*A_ + a];
    __syncthreads();
    const float* wr = Wq + a*A_;
    float s = 0.f;
    #pragma unroll 8
    for (int i = 0; i < A_; i++) s += sh[i]*wr[i];
    g_pq[b*A_ + a] = s;
}
__global__ void wmh_kernel(const float* __restrict__ Wm) {
    int i = blockIdx.x*256 + threadIdx.x;
    g_wmh[i] = __float2half_rn(Wm[i]);
}
__global__ void wclh_kernel(const float* __restrict__ Wl, const float* __restrict__ convw) {
    const int j = blockIdx.x;   // 0..63
    const int a = threadIdx.x;  // 0..127
    float s = 0.f;
    if (j < 62) {
        int c = j / K_, k = j % K_;
        #pragma unroll
        for (int f = 0; f < NF_; f++) s += Wl[a*NF_ + f]*convw[f*(2*K_) + c*K_ + k];
    }
    g_wclh[a*64 + j] = __float2half_rn(s);
}

// ---------------- pipelined HMMA energies kernel ----------------
// CTA = (b, 128-t tile). D[t][a] = sum_{k<576} A[t,k]*B[a,k]; A split fp16 hi/lo (exact),
// B single fp16 (err 2^-12). Chunks 0..7: pm, chunk 8: folded location.
__global__ __launch_bounds__(256, 1)
void energies_mma_kernel(const float* __restrict__ pmem,
                         const float* __restrict__ awc,
                         const float* __restrict__ v)
{
    extern __shared__ char smem[];
    const uint32_t sb = smem_u32(smem);
    const int tid = threadIdx.x;
    const int wid = tid >> 5, lane = tid & 31;
    const int b = blockIdx.y, t0 = blockIdx.x*128;
    const int warp_m = wid & 1, warp_n = wid >> 1;
    const int mb = warp_m*64, nb = warp_n*32;

    float* s_awc  = (float*)(smem + OFF_AWC);
    float* s_pq   = (float*)(smem + OFF_PQ);
    float* s_v    = (float*)(smem + OFF_V);
    float* s_part = (float*)(smem + OFF_PART);

    for (int i = tid; i < 320; i += 256) {
        int c = i / 160, x = i % 160, t = t0 - 15 + x;
        s_awc[i] = (x < 158 && t >= 0 && t < T_) ? awc[((size_t)b*2 + c)*T_ + t] : 0.f;
    }
    if (tid < A_) { s_pq[tid] = g_pq[b*A_ + tid]; s_v[tid] = v[tid]; }

    float acc[4][4][4];
    #pragma unroll
    for (int i = 0; i < 4; i++)
        #pragma unroll
        for (int j = 0; j < 4; j++)
            #pragma unroll
            for (int q = 0; q < 4; q++) acc[i][j][q] = 0.f;

    const float* PMb = pmem + ((size_t)b*T_ + t0)*E_;
    const int r8 = tid >> 3, g8 = tid & 7;     // 128 rows x 8 groups (16B), 2 rounds of 4 its

    // ---- prologue: cp.async B(0), LDG-prefetch A(0) ----
    {
        #pragma unroll
        for (int it = 0; it < 4; it++) {
            int idx = tid + 256*it, r = idx >> 3, g = idx & 7;
            CPASYNC16(tile_addr(sb + OFF_B0, r, g*16), (const void*)(g_wmh + (size_t)r*E_ + g*8));
        }
        CPCOMMIT();
    }
    float4 pf[8];
    #pragma unroll
    for (int it = 0; it < 4; it++) {
        int idx = tid + 256*it, r = idx >> 3, g = idx & 7;
        const float4* p = (const float4*)(PMb + (size_t)r*E_ + g*8);
        pf[it*2]   = p[0];
        pf[it*2+1] = p[1];
    }

    for (int ch = 0; ch < 9; ch++) {
        const int p = ch & 1;
        const uint32_t baseAH = sb + (p ? OFF_AH1 : OFF_AH0);
        const uint32_t baseAL = sb + (p ? OFF_AL1 : OFF_AL0);
        const uint32_t baseB  = sb + (p ? OFF_B1  : OFF_B0);

        // ---- convert + STS A(ch) ----
        if (ch < 8) {
            #pragma unroll
            for (int it = 0; it < 4; it++) {
                int idx = tid + 256*it, r = idx >> 3, g = idx & 7;
                float4 x0 = pf[it*2], x1 = pf[it*2+1];
                uint32_t h0,h1,h2,h3,l0,l1,l2,l3;
                split2h(x0.x, x0.y, h0, l0); split2h(x0.z, x0.w, h1, l1);
                split2h(x1.x, x1.y, h2, l2); split2h(x1.z, x1.w, h3, l3);
                STS128(tile_addr(baseAH, r, g*16), h0, h1, h2, h3);
                STS128(tile_addr(baseAL, r, g*16), l0, l1, l2, l3);
            }
        } else {
            const int r = tid >> 1, jb = (tid & 1)*32;
            #pragma unroll
            for (int jj = 0; jj < 32; jj += 8) {
                uint32_t hw[4], lw[4];
                #pragma unroll
                for (int q = 0; q < 4; q++) {
                    int j0 = jb + jj + 2*q;
                    split2h(locval(s_awc, r, j0), locval(s_awc, r, j0 + 1), hw[q], lw[q]);
                }
                STS128(tile_addr(baseAH, r, (jb + jj)*2), hw[0], hw[1], hw[2], hw[3]);
                STS128(tile_addr(baseAL, r, (jb + jj)*2), lw[0], lw[1], lw[2], lw[3]);
            }
        }

        // ---- issue next-chunk loads ----
        if (ch < 8) {
            const uint32_t baseBn = sb + ((ch & 1) ? OFF_B0 : OFF_B1);
            if (ch + 1 < 8) {
                const int e0n = (ch + 1)*64;
                #pragma unroll
                for (int it = 0; it < 4; it++) {
                    int idx = tid + 256*it, r = idx >> 3, g = idx & 7;
                    CPASYNC16(tile_addr(baseBn, r, g*16),
                              (const void*)(g_wmh + (size_t)r*E_ + e0n + g*8));
                }
                CPCOMMIT();
                #pragma unroll
                for (int it = 0; it < 4; it++) {
                    int idx = tid + 256*it, r = idx >> 3, g = idx & 7;
                    const float4* ptr = (const float4*)(PMb + (size_t)r*E_ + e0n + g*8);
                    pf[it*2]   = ptr[0];
                    pf[it*2+1] = ptr[1];
                }
            } else {
                #pragma unroll
                for (int it = 0; it < 4; it++) {
                    int idx = tid + 256*it, r = idx >> 3, g = idx & 7;
                    CPASYNC16(tile_addr(baseBn, r, g*16),
                              (const void*)(g_wclh + (size_t)r*64 + g*8));
                }
                CPCOMMIT();
            }
            asm volatile("cp.async.wait_group 1;" ::: "memory");
        } else {
            asm volatile("cp.async.wait_group 0;" ::: "memory");
        }
        __syncthreads();

        // ---- compute: 4 k16 steps x (Ah.B + Al.B) ----
        #pragma unroll
        for (int ks = 0; ks < 4; ks++) {
            const int kb = ks*16;
            uint32_t ah[4][4], al[4][4], bf[2][4];
            #pragma unroll
            for (int i = 0; i < 4; i++) {
                ldsm_x4(ah[i], ldsm_addr(baseAH, mb + 16*i, kb, lane));
                ldsm_x4(al[i], ldsm_addr(baseAL, mb + 16*i, kb, lane));
            }
            #pragma unroll
            for (int j2 = 0; j2 < 2; j2++)
                ldsm_x4(bf[j2], ldsm_addr(baseB, nb + 16*j2, kb, lane));
            #pragma unroll
            for (int i = 0; i < 4; i++) {
                #pragma unroll
                for (int j = 0; j < 4; j++) {
                    const int j2 = j >> 1, jo = j & 1;
                    mma_f16(acc[i][j], ah[i], bf[j2][jo], bf[j2][jo+2]);
                    mma_f16(acc[i][j], al[i], bf[j2][jo], bf[j2][jo+2]);
                }
            }
        }
        if (ch < 8) __syncthreads();   // bufs ping-pong; next STS targets other buffer
    }

    // ---- epilogue: energy[t] = sum_a v[a]*tanh(D[t][a] + pq[a]) ----
    #pragma unroll
    for (int i = 0; i < 4; i++) {
        #pragma unroll
        for (int half = 0; half < 2; half++) {
            float s = 0.f;
            #pragma unroll
            for (int j = 0; j < 4; j++) {
                const int a0 = nb + j*8 + (lane & 3)*2;
                float x0 = acc[i][j][half*2+0] + s_pq[a0];
                float x1 = acc[i][j][half*2+1] + s_pq[a0+1];
                s += s_v[a0]*tanh_fast(x0) + s_v[a0+1]*tanh_fast(x1);
            }
            s += __shfl_xor_sync(0xffffffffu, s, 1);
            s += __shfl_xor_sync(0xffffffffu, s, 2);
            if ((lane & 3) == 0) {
                int row = mb + i*16 + (lane >> 2) + half*8;
                s_part[row*4 + warp_n] = s;
            }
        }
    }
    __syncthreads();
    if (tid < 128) {
        const float* pp = s_part + tid*4;
        g_energies[(size_t)b*T_ + t0 + tid] = (pp[0] + pp[1]) + (pp[2] + pp[3]);
    }
}

// ---------------- masked softmax over T ----------------
__global__ void softmax_kernel(const int* __restrict__ mask, float* __restrict__ wout) {
    const int b = blockIdx.x, tid = threadIdx.x;
    __shared__ float red[256];
    float e[4];
    float mx = -INFINITY;
    #pragma unroll
    for (int q = 0; q < 4; q++) {
        int t = tid + 256*q;
        float ev = g_energies[b*T_ + t];
        if (mask[b*T_ + t] != 0) ev = -INFINITY;
        e[q] = ev;
        mx = fmaxf(mx, ev);
    }
    red[tid] = mx; __syncthreads();
    for (int s = 128; s > 0; s >>= 1) {
        if (tid < s) red[tid] = fmaxf(red[tid], red[tid + s]);
        __syncthreads();
    }
    const float m = red[0];
    __syncthreads();
    float ex[4], sum = 0.f;
    #pragma unroll
    for (int q = 0; q < 4; q++) {
        ex[q] = (e[q] == -INFINITY) ? 0.f : expf(e[q] - m);
        sum += ex[q];
    }
    red[tid] = sum; __syncthreads();
    for (int s = 128; s > 0; s >>= 1) {
        if (tid < s) red[tid] += red[tid + s];
        __syncthreads();
    }
    const float inv = 1.f / red[0];
    #pragma unroll
    for (int q = 0; q < 4; q++) wout[b*T_ + tid + 256*q] = ex[q]*inv;
}

// ---------------- context: segmented partials + deterministic reduce ----------------
__global__ void context_part_kernel(const float* __restrict__ mem,
                                    const float* __restrict__ w)
{
    __shared__ float sw[128];
    const int b = blockIdx.z, seg = blockIdx.y;
    const int e = blockIdx.x*256 + threadIdx.x;
    const int t0 = seg*128;
    if (threadIdx.x < 128) sw[threadIdx.x] = w[b*T_ + t0 + threadIdx.x];
    __syncthreads();
    const float* mb = mem + ((size_t)b*T_ + t0)*E_ + e;
    float a0 = 0.f, a1 = 0.f, a2 = 0.f, a3 = 0.f;
    #pragma unroll 4
    for (int t = 0; t < 128; t += 4) {
        float w0 = sw[t], w1 = sw[t+1], w2 = sw[t+2], w3 = sw[t+3];
        if (w0 != 0.f) a0 += w0*mb[(size_t)(t  )*E_];
        if (w1 != 0.f) a1 += w1*mb[(size_t)(t+1)*E_];
        if (w2 != 0.f) a2 += w2*mb[(size_t)(t+2)*E_];
        if (w3 != 0.f) a3 += w3*mb[(size_t)(t+3)*E_];
    }
    g_cpart[((size_t)seg*B_ + b)*E_ + e] = (a0 + a1) + (a2 + a3);
}
__global__ void context_reduce_kernel(float* __restrict__ ctx) {
    const int i = blockIdx.x*256 + threadIdx.x;   // over B*E
    float s = 0.f;
    #pragma unroll
    for (int seg = 0; seg < SEG_; seg++) s += g_cpart[(size_t)seg*B_*E_ + i];
    ctx[i] = s;
}

// ---------------- launch ----------------
extern "C" void kernel_launch(void* const* d_in, const int* in_sizes, int n_in,
                              void* d_out, int out_size)
{
    const float* ahs   = (const float*)d_in[0];   // [B, A]
    const float* mem   = (const float*)d_in[1];   // [B, T, E]
    const float* pmem  = (const float*)d_in[2];   // [B, T, E]
    const float* awc   = (const float*)d_in[3];   // [B, 2, T]
    const int*   mask  = (const int*)d_in[4];     // [B, T] bool -> int32
    const float* Wq    = (const float*)d_in[5];   // [A, A]
    const float* Wm    = (const float*)d_in[6];   // [A, E]
    const float* v     = (const float*)d_in[7];   // [1, A]
    const float* convw = (const float*)d_in[8];   // [NF, 2, K]
    const float* Wl    = (const float*)d_in[9];   // [A, NF]

    float* out_ctx = (float*)d_out;            // [B, E]
    float* out_w   = (float*)d_out + B_*E_;    // [B, T]

    cudaFuncSetAttribute(energies_mma_kernel,
                         cudaFuncAttributeMaxDynamicSharedMemorySize, SMEM_TOTAL);

    pq_kernel<<<B_, A_>>>(ahs, Wq);
    wmh_kernel<<<(A_*E_)/256, 256>>>(Wm);
    wclh_kernel<<<64, A_>>>(Wl, convw);
    energies_mma_kernel<<<dim3(T_/128, B_), 256, SMEM_TOTAL>>>(pmem, awc, v);
    softmax_kernel<<<B_, 256>>>(mask, out_w);
    context_part_kernel<<<dim3(E_/256, SEG_, B_), 256>>>(mem, out_w);
    context_reduce_kernel<<<(B_*E_)/256, 256>>>(out_ctx);
}

// round 6
// speedup vs baseline: 4.2262x; 1.2873x over previous
#include <cuda_runtime.h>
#include <cuda_fp16.h>
#include <cstdint>
#include <math.h>

#define B_  64
#define T_  1024
#define E_  512
#define A_  128
#define NF_ 32
#define K_  31
#define SEG_ 8

// ---------------- smem layout (dynamic) ----------------
#define OFF_AH0 0
#define OFF_AL0 16384
#define OFF_AH1 32768
#define OFF_AL1 49152
#define OFF_B0  65536
#define OFF_B1  81920
#define OFF_AWC 98304            // 2048 floats (full awc[b], both channels)
#define OFF_PQ  106496           // 128 floats
#define OFF_V   107008           // 128 floats
#define OFF_PART 107520          // 512 floats
#define OFF_TIDX 109568          // 128 ints
#define SMEM_TOTAL 110080

// ---------------- scratch ----------------
__device__ float g_pq[B_*A_];
__device__ float g_energies[B_*T_];
__device__ __align__(16) __half g_wmh[A_*E_];     // fp16(Wm)
__device__ __align__(16) __half g_wclh[A_*64];    // fp16(folded Wl@conv_w), [a][j] padded 64
__device__ float g_cpart[SEG_*B_*E_];
__device__ int g_cnt[B_];
__device__ int g_tidx[B_*T_];

// ---------------- helpers ----------------
__device__ __forceinline__ uint32_t smem_u32(const void* p) {
    uint32_t a;
    asm("{ .reg .u64 t; cvta.to.shared.u64 t, %1; cvt.u32.u64 %0, t; }" : "=r"(a) : "l"(p));
    return a;
}
#define STS128(addr, a, b, c, d) \
    asm volatile("st.shared.v4.b32 [%0], {%1,%2,%3,%4};" :: "r"(addr), "r"(a), "r"(b), "r"(c), "r"(d) : "memory")
#define CPASYNC16(dst, src) \
    asm volatile("cp.async.ca.shared.global [%0], [%1], 16;" :: "r"(dst), "l"(src) : "memory")
#define CPCOMMIT() asm volatile("cp.async.commit_group;" ::: "memory")

__device__ __forceinline__ void ldsm_x4(uint32_t (&r)[4], uint32_t addr) {
    asm volatile("ldmatrix.sync.aligned.m8n8.x4.shared.b16 {%0,%1,%2,%3}, [%4];"
        : "=r"(r[0]), "=r"(r[1]), "=r"(r[2]), "=r"(r[3]) : "r"(addr));
}
__device__ __forceinline__ void mma_f16(float (&c)[4], const uint32_t (&a)[4],
                                        uint32_t b0, uint32_t b1) {
    asm volatile("mma.sync.aligned.m16n8k16.row.col.f32.f16.f16.f32 "
        "{%0,%1,%2,%3}, {%4,%5,%6,%7}, {%8,%9}, {%0,%1,%2,%3};"
        : "+f"(c[0]), "+f"(c[1]), "+f"(c[2]), "+f"(c[3])
        : "r"(a[0]), "r"(a[1]), "r"(a[2]), "r"(a[3]), "r"(b0), "r"(b1));
}
// byte address inside a 128-row x 128-byte smem tile, SW128 swizzle
__device__ __forceinline__ uint32_t tile_addr(uint32_t base, int row, int kbyte) {
    uint32_t off = (uint32_t)(row*128 + kbyte);
    return base + (off ^ ((off >> 3) & 0x70));
}
__device__ __forceinline__ uint32_t ldsm_addr(uint32_t base, int rb, int kb, int lane) {
    int row = rb + (lane & 15);
    int kbyte = (kb + (lane >> 4)*8)*2;
    return tile_addr(base, row, kbyte);
}
__device__ __forceinline__ void split2h(float a, float b, uint32_t& h, uint32_t& l) {
    __half ha = __float2half_rn(a), hb = __float2half_rn(b);
    __half la = __float2half_rn(a - __half2float(ha));
    __half lb = __float2half_rn(b - __half2float(hb));
    __half2 hp = __halves2half2(ha, hb), lp = __halves2half2(la, lb);
    h = *reinterpret_cast<uint32_t*>(&hp);
    l = *reinterpret_cast<uint32_t*>(&lp);
}
__device__ __forceinline__ float tanh_fast(float x) {
    float e = __expf(fminf(fmaxf(2.f*x, -30.f), 30.f));
    return 1.f - __fdividef(2.f, e + 1.f);
}
// location term value for original position tor, tap j (full awc[b] in smem)
__device__ __forceinline__ float locval(const float* s_awc, int tor, int j) {
    if (j >= 62) return 0.f;
    int c = (j >= 31) ? 1 : 0;
    int k = j - c*31;
    int t = tor - 15 + k;
    return (t >= 0 && t < T_) ? s_awc[c*T_ + t] : 0.f;
}

// ---------------- prep kernels ----------------
__global__ void pq_kernel(const float* __restrict__ ahs, const float* __restrict__ Wq) {
    __shared__ float sh[A_];
    const int b = blockIdx.x, a = threadIdx.x;
    sh[a] = ahs[b*A_ + a];
    __syncthreads();
    const float* wr = Wq + a*A_;
    float s = 0.f;
    #pragma unroll 8
    for (int i = 0; i < A_; i++) s += sh[i]*wr[i];
    g_pq[b*A_ + a] = s;
}
__global__ void wmh_kernel(const float* __restrict__ Wm) {
    int i = blockIdx.x*256 + threadIdx.x;
    g_wmh[i] = __float2half_rn(Wm[i]);
}
__global__ void wclh_kernel(const float* __restrict__ Wl, const float* __restrict__ convw) {
    const int j = blockIdx.x;   // 0..63
    const int a = threadIdx.x;  // 0..127
    float s = 0.f;
    if (j < 62) {
        int c = j / K_, k = j % K_;
        #pragma unroll
        for (int f = 0; f < NF_; f++) s += Wl[a*NF_ + f]*convw[f*(2*K_) + c*K_ + k];
    }
    g_wclh[a*64 + j] = __float2half_rn(s);
}

// ---------------- mask compaction: list of unmasked t per batch ----------------
__global__ void compact_kernel(const int* __restrict__ mask) {
    const int b = blockIdx.x, tid = threadIdx.x;   // 256 threads
    __shared__ int s1[256], s2[256];
    int loc[4]; int c = 0;
    #pragma unroll
    for (int q = 0; q < 4; q++) {
        int t = tid*4 + q;
        if (mask[b*T_ + t] == 0) loc[c++] = t;
    }
    s1[tid] = c; __syncthreads();
    int* src = s1; int* dst = s2;
    #pragma unroll
    for (int off = 1; off < 256; off <<= 1) {
        int vv = src[tid];
        if (tid >= off) vv += src[tid - off];
        dst[tid] = vv;
        __syncthreads();
        int* tmp = src; src = dst; dst = tmp;
    }
    int base = src[tid] - c;
    for (int i = 0; i < c; i++) g_tidx[b*T_ + base + i] = loc[i];
    if (tid == 255) g_cnt[b] = src[255];
}

// ---------------- pipelined HMMA energies kernel (compacted rows) ----------------
// CTA = (b, 128 compacted-t rows). D[r][a] = sum_{k<576} A[r,k]*B[a,k];
// A split fp16 hi/lo (exact), B single fp16. Chunks 0..7: pm, chunk 8: location.
__global__ __launch_bounds__(256, 1)
void energies_mma_kernel(const float* __restrict__ pmem,
                         const float* __restrict__ awc,
                         const float* __restrict__ v)
{
    extern __shared__ char smem[];
    const uint32_t sb = smem_u32(smem);
    const int tid = threadIdx.x;
    const int wid = tid >> 5, lane = tid & 31;
    const int b = blockIdx.y, t0 = blockIdx.x*128;
    const int cnt = g_cnt[b];
    if (t0 >= cnt) return;
    const int warp_m = wid & 1, warp_n = wid >> 1;
    const int mb = warp_m*64, nb = warp_n*32;

    float* s_awc  = (float*)(smem + OFF_AWC);
    float* s_pq   = (float*)(smem + OFF_PQ);
    float* s_v    = (float*)(smem + OFF_V);
    float* s_part = (float*)(smem + OFF_PART);
    int*   s_tidx = (int*)(smem + OFF_TIDX);

    // ---- cp.async B(0) (independent of smem metadata) ----
    #pragma unroll
    for (int it = 0; it < 4; it++) {
        int idx = tid + 256*it, r = idx >> 3, g = idx & 7;
        CPASYNC16(tile_addr(sb + OFF_B0, r, g*16), (const void*)(g_wmh + (size_t)r*E_ + g*8));
    }
    CPCOMMIT();

    // ---- stage metadata ----
    if (tid < 128) {
        int t = (t0 + tid < cnt) ? g_tidx[b*T_ + t0 + tid] : 0;
        s_tidx[tid] = t;
    }
    for (int i = tid; i < 2*T_; i += 256) s_awc[i] = awc[(size_t)b*2*T_ + i];
    if (tid < A_) { s_pq[tid] = g_pq[b*A_ + tid]; s_v[tid] = v[tid]; }
    __syncthreads();

    // per-thread A-row base pointers (rows r = (tid>>3) + 32*it), col offset (tid&7)*8
    const float* rowp[4];
    #pragma unroll
    for (int it = 0; it < 4; it++) {
        int r = (tid >> 3) + 32*it;
        rowp[it] = pmem + ((size_t)b*T_ + s_tidx[r])*E_ + (tid & 7)*8;
    }

    float acc[4][4][4];
    #pragma unroll
    for (int i = 0; i < 4; i++)
        #pragma unroll
        for (int j = 0; j < 4; j++)
            #pragma unroll
            for (int q = 0; q < 4; q++) acc[i][j][q] = 0.f;

    // ---- prologue: LDG-prefetch A(0) ----
    float4 pf[8];
    #pragma unroll
    for (int it = 0; it < 4; it++) {
        const float4* p = (const float4*)rowp[it];
        pf[it*2]   = p[0];
        pf[it*2+1] = p[1];
    }

    for (int ch = 0; ch < 9; ch++) {
        const int p = ch & 1;
        const uint32_t baseAH = sb + (p ? OFF_AH1 : OFF_AH0);
        const uint32_t baseAL = sb + (p ? OFF_AL1 : OFF_AL0);
        const uint32_t baseB  = sb + (p ? OFF_B1  : OFF_B0);

        // ---- convert + STS A(ch) ----
        if (ch < 8) {
            #pragma unroll
            for (int it = 0; it < 4; it++) {
                int idx = tid + 256*it, r = idx >> 3, g = idx & 7;
                float4 x0 = pf[it*2], x1 = pf[it*2+1];
                uint32_t h0,h1,h2,h3,l0,l1,l2,l3;
                split2h(x0.x, x0.y, h0, l0); split2h(x0.z, x0.w, h1, l1);
                split2h(x1.x, x1.y, h2, l2); split2h(x1.z, x1.w, h3, l3);
                STS128(tile_addr(baseAH, r, g*16), h0, h1, h2, h3);
                STS128(tile_addr(baseAL, r, g*16), l0, l1, l2, l3);
            }
        } else {
            const int r = tid >> 1, jb = (tid & 1)*32;
            const int tor = s_tidx[r];
            #pragma unroll
            for (int jj = 0; jj < 32; jj += 8) {
                uint32_t hw[4], lw[4];
                #pragma unroll
                for (int q = 0; q < 4; q++) {
                    int j0 = jb + jj + 2*q;
                    split2h(locval(s_awc, tor, j0), locval(s_awc, tor, j0 + 1), hw[q], lw[q]);
                }
                STS128(tile_addr(baseAH, r, (jb + jj)*2), hw[0], hw[1], hw[2], hw[3]);
                STS128(tile_addr(baseAL, r, (jb + jj)*2), lw[0], lw[1], lw[2], lw[3]);
            }
        }

        // ---- issue next-chunk loads ----
        if (ch < 8) {
            const uint32_t baseBn = sb + ((ch & 1) ? OFF_B0 : OFF_B1);
            if (ch + 1 < 8) {
                const int e0n = (ch + 1)*64;
                #pragma unroll
                for (int it = 0; it < 4; it++) {
                    int idx = tid + 256*it, r = idx >> 3, g = idx & 7;
                    CPASYNC16(tile_addr(baseBn, r, g*16),
                              (const void*)(g_wmh + (size_t)r*E_ + e0n + g*8));
                }
                CPCOMMIT();
                #pragma unroll
                for (int it = 0; it < 4; it++) {
                    const float4* ptr = (const float4*)(rowp[it] + e0n);
                    pf[it*2]   = ptr[0];
                    pf[it*2+1] = ptr[1];
                }
            } else {
                #pragma unroll
                for (int it = 0; it < 4; it++) {
                    int idx = tid + 256*it, r = idx >> 3, g = idx & 7;
                    CPASYNC16(tile_addr(baseBn, r, g*16),
                              (const void*)(g_wclh + (size_t)r*64 + g*8));
                }
                CPCOMMIT();
            }
            asm volatile("cp.async.wait_group 1;" ::: "memory");
        } else {
            asm volatile("cp.async.wait_group 0;" ::: "memory");
        }
        __syncthreads();

        // ---- compute: 4 k16 steps x (Ah.B + Al.B) ----
        #pragma unroll
        for (int ks = 0; ks < 4; ks++) {
            const int kb = ks*16;
            uint32_t ah[4][4], al[4][4], bf[2][4];
            #pragma unroll
            for (int i = 0; i < 4; i++) {
                ldsm_x4(ah[i], ldsm_addr(baseAH, mb + 16*i, kb, lane));
                ldsm_x4(al[i], ldsm_addr(baseAL, mb + 16*i, kb, lane));
            }
            #pragma unroll
            for (int j2 = 0; j2 < 2; j2++)
                ldsm_x4(bf[j2], ldsm_addr(baseB, nb + 16*j2, kb, lane));
            #pragma unroll
            for (int i = 0; i < 4; i++) {
                #pragma unroll
                for (int j = 0; j < 4; j++) {
                    const int j2 = j >> 1, jo = j & 1;
                    mma_f16(acc[i][j], ah[i], bf[j2][jo], bf[j2][jo+2]);
                    mma_f16(acc[i][j], al[i], bf[j2][jo], bf[j2][jo+2]);
                }
            }
        }
        if (ch < 8) __syncthreads();   // ping-pong: next STS targets other buffer
    }

    // ---- epilogue: energy[r] = sum_a v[a]*tanh(D[r][a] + pq[a]) ----
    #pragma unroll
    for (int i = 0; i < 4; i++) {
        #pragma unroll
        for (int half = 0; half < 2; half++) {
            float s = 0.f;
            #pragma unroll
            for (int j = 0; j < 4; j++) {
                const int a0 = nb + j*8 + (lane & 3)*2;
                float x0 = acc[i][j][half*2+0] + s_pq[a0];
                float x1 = acc[i][j][half*2+1] + s_pq[a0+1];
                s += s_v[a0]*tanh_fast(x0) + s_v[a0+1]*tanh_fast(x1);
            }
            s += __shfl_xor_sync(0xffffffffu, s, 1);
            s += __shfl_xor_sync(0xffffffffu, s, 2);
            if ((lane & 3) == 0) {
                int row = mb + i*16 + (lane >> 2) + half*8;
                s_part[row*4 + warp_n] = s;
            }
        }
    }
    __syncthreads();
    if (tid < 128 && t0 + tid < cnt) {
        const float* pp = s_part + tid*4;
        g_energies[(size_t)b*T_ + s_tidx[tid]] = (pp[0] + pp[1]) + (pp[2] + pp[3]);
    }
}

// ---------------- masked softmax over T ----------------
__global__ void softmax_kernel(const int* __restrict__ mask, float* __restrict__ wout) {
    const int b = blockIdx.x, tid = threadIdx.x;
    __shared__ float red[256];
    float e[4];
    float mx = -INFINITY;
    #pragma unroll
    for (int q = 0; q < 4; q++) {
        int t = tid + 256*q;
        float ev = g_energies[b*T_ + t];
        if (mask[b*T_ + t] != 0) ev = -INFINITY;
        e[q] = ev;
        mx = fmaxf(mx, ev);
    }
    red[tid] = mx; __syncthreads();
    for (int s = 128; s > 0; s >>= 1) {
        if (tid < s) red[tid] = fmaxf(red[tid], red[tid + s]);
        __syncthreads();
    }
    const float m = red[0];
    __syncthreads();
    float ex[4], sum = 0.f;
    #pragma unroll
    for (int q = 0; q < 4; q++) {
        ex[q] = (e[q] == -INFINITY) ? 0.f : expf(e[q] - m);
        sum += ex[q];
    }
    red[tid] = sum; __syncthreads();
    for (int s = 128; s > 0; s >>= 1) {
        if (tid < s) red[tid] += red[tid + s];
        __syncthreads();
    }
    const float inv = 1.f / red[0];
    #pragma unroll
    for (int q = 0; q < 4; q++) wout[b*T_ + tid + 256*q] = ex[q]*inv;
}

// ---------------- context: segmented partials + deterministic reduce ----------------
__global__ void context_part_kernel(const float* __restrict__ mem,
                                    const float* __restrict__ w)
{
    __shared__ float sw[128];
    const int b = blockIdx.z, seg = blockIdx.y;
    const int e = blockIdx.x*256 + threadIdx.x;
    const int t0 = seg*128;
    if (threadIdx.x < 128) sw[threadIdx.x] = w[b*T_ + t0 + threadIdx.x];
    __syncthreads();
    const float* mb = mem + ((size_t)b*T_ + t0)*E_ + e;
    float a0 = 0.f, a1 = 0.f, a2 = 0.f, a3 = 0.f;
    #pragma unroll 4
    for (int t = 0; t < 128; t += 4) {
        float w0 = sw[t], w1 = sw[t+1], w2 = sw[t+2], w3 = sw[t+3];
        if (w0 != 0.f) a0 += w0*mb[(size_t)(t  )*E_];
        if (w1 != 0.f) a1 += w1*mb[(size_t)(t+1)*E_];
        if (w2 != 0.f) a2 += w2*mb[(size_t)(t+2)*E_];
        if (w3 != 0.f) a3 += w3*mb[(size_t)(t+3)*E_];
    }
    g_cpart[((size_t)seg*B_ + b)*E_ + e] = (a0 + a1) + (a2 + a3);
}
__global__ void context_reduce_kernel(float* __restrict__ ctx) {
    const int i = blockIdx.x*256 + threadIdx.x;   // over B*E
    float s = 0.f;
    #pragma unroll
    for (int seg = 0; seg < SEG_; seg++) s += g_cpart[(size_t)seg*B_*E_ + i];
    ctx[i] = s;
}

// ---------------- launch ----------------
extern "C" void kernel_launch(void* const* d_in, const int* in_sizes, int n_in,
                              void* d_out, int out_size)
{
    const float* ahs   = (const float*)d_in[0];   // [B, A]
    const float* mem   = (const float*)d_in[1];   // [B, T, E]
    const float* pmem  = (const float*)d_in[2];   // [B, T, E]
    const float* awc   = (const float*)d_in[3];   // [B, 2, T]
    const int*   mask  = (const int*)d_in[4];     // [B, T] bool -> int32
    const float* Wq    = (const float*)d_in[5];   // [A, A]
    const float* Wm    = (const float*)d_in[6];   // [A, E]
    const float* v     = (const float*)d_in[7];   // [1, A]
    const float* convw = (const float*)d_in[8];   // [NF, 2, K]
    const float* Wl    = (const float*)d_in[9];   // [A, NF]

    float* out_ctx = (float*)d_out;            // [B, E]
    float* out_w   = (float*)d_out + B_*E_;    // [B, T]

    cudaFuncSetAttribute(energies_mma_kernel,
                         cudaFuncAttributeMaxDynamicSharedMemorySize, SMEM_TOTAL);

    compact_kernel<<<B_, 256>>>(mask);
    pq_kernel<<<B_, A_>>>(ahs, Wq);
    wmh_kernel<<<(A_*E_)/256, 256>>>(Wm);
    wclh_kernel<<<64, A_>>>(Wl, convw);
    energies_mma_kernel<<<dim3(T_/128, B_), 256, SMEM_TOTAL>>>(pmem, awc, v);
    softmax_kernel<<<B_, 256>>>(mask, out_w);
    context_part_kernel<<<dim3(E_/256, SEG_, B_), 256>>>(mem, out_w);
    context_reduce_kernel<<<(B_*E_)/256, 256>>>(out_ctx);
}